// round 2
// baseline (speedup 1.0000x reference)
#include <cuda_runtime.h>
#include <cuda_bf16.h>

#define SS   1024      // S = 2*max(H,W)
#define HH   512
#define WW   512
#define BB   32
#define OFFC 256       // (S-H)/2 = (S-W)/2

__global__ __launch_bounds__(256)
void gridmask_kernel(const float* __restrict__ img,
                     const float* __restrict__ angles,
                     const int*   __restrict__ gridblock,
                     const int*   __restrict__ start1,
                     const int*   __restrict__ start2,
                     float*       __restrict__ out) {
    __shared__ float rowm[SS];
    __shared__ float colm[SS];
    __shared__ float s_trig[2];

    const int b   = blockIdx.y;
    const int gb  = gridblock[b];
    const int st1 = start1[b];
    const int st2 = start2[b];

    // length = clip(int(gb*0.6 + 0.5), 1, gb-1)  -- match f32 mul then add, truncate
    float lf = __fadd_rn(__fmul_rn((float)gb, 0.6f), 0.5f);
    int length = (int)lf;
    length = min(max(length, 1), gb - 1);
    const int lim = (SS / gb) * gb;          // d//gb < n  <=>  d < n*gb (d>=0)
    // magic reciprocal: exact d/gb for 0 <= d < 2048, gb >= 2
    const unsigned M = (1u << 22) / (unsigned)gb + 1u;

    if (threadIdx.x == 0) {
        float a = angles[b];
        s_trig[0] = cosf(a);
        s_trig[1] = sinf(a);
    }
    // Build separable stripe LUTs (no hardware integer division)
    for (int i = threadIdx.x; i < SS; i += blockDim.x) {
        int d1 = i - st1;
        unsigned u1 = (unsigned)d1;
        unsigned q1 = (u1 * M) >> 22;
        unsigned rem1 = u1 - q1 * (unsigned)gb;
        rowm[i] = (d1 >= 0 && d1 < lim && rem1 < (unsigned)length) ? 1.0f : 0.0f;

        int d2 = i - st2;
        unsigned u2 = (unsigned)d2;
        unsigned q2 = (u2 * M) >> 22;
        unsigned rem2 = u2 - q2 * (unsigned)gb;
        colm[i] = (d2 >= 0 && d2 < lim && rem2 < (unsigned)length) ? 1.0f : 0.0f;
    }
    __syncthreads();

    const float cosv = s_trig[0];
    const float sinv = s_trig[1];
    const float c = (float)(SS - 1) * 0.5f;   // 511.5

    const int ROWS = 8;
    const int row0 = blockIdx.x * ROWS;
    const float* imgb = img + (size_t)b * HH * WW * 3;
    float*       outb = out + (size_t)b * HH * WW * 3;

    // Each iteration: 4 consecutive pixels = 12 floats = 3 float4 (48B, aligned)
    const int NGROUPS = (ROWS * WW) / 4;   // 1024
    for (int g = threadIdx.x; g < NGROUPS; g += blockDim.x) {
        const int p0 = g * 4;
        const int h  = row0 + (p0 >> 9);      // / WW
        const int w  = p0 & (WW - 1);
        const float y = (float)(h + OFFC) - c;
        // hoist y-dependent rotation terms
        const float sxc =  sinv * y + c;      // sx = cosv*x + sxc
        const float syc =  cosv * y + c;      // sy = -sinv*x + syc
        const float xb  = (float)(w + OFFC) - c;

        float m[4];
        #pragma unroll
        for (int k = 0; k < 4; k++) {
            float x  = xb + (float)k;
            float sx = fmaf(cosv, x, sxc);
            float sy = fmaf(-sinv, x, syc);
            // sampled coords are provably within [150, 873]: reflection never
            // triggers (max rotation radius sqrt(2)*255.5 = 361.3 < 511.5)
            float x0f = floorf(sx), y0f = floorf(sy);
            float fx = sx - x0f,    fy = sy - y0f;
            int x0 = (int)x0f, y0 = (int)y0f;
            float r0 = rowm[y0], r1 = rowm[y0 + 1];
            float c0 = colm[x0], c1 = colm[x0 + 1];
            // binary OR: v = r + c - r*c; weights separable =>
            // m = R + C - R*C,  R = lerp(r0,r1,fy), C = lerp(c0,c1,fx)
            float R = fmaf(fy, r1 - r0, r0);
            float C = fmaf(fx, c1 - c0, c0);
            m[k] = fmaf(C, 1.0f - R, R);
        }

        const size_t base = ((size_t)h * WW + w) * 3;
        float4* dst = reinterpret_cast<float4*>(outb + base);

        if (m[0] == 0.0f && m[1] == 0.0f && m[2] == 0.0f && m[3] == 0.0f) {
            // exact zero region: skip the image read entirely
            float4 z = make_float4(0.f, 0.f, 0.f, 0.f);
            dst[0] = z; dst[1] = z; dst[2] = z;
        } else {
            const float4* src = reinterpret_cast<const float4*>(imgb + base);
            float4 a0 = src[0], a1 = src[1], a2 = src[2];
            dst[0] = make_float4(a0.x * m[0], a0.y * m[0], a0.z * m[0], a0.w * m[1]);
            dst[1] = make_float4(a1.x * m[1], a1.y * m[1], a1.z * m[2], a1.w * m[2]);
            dst[2] = make_float4(a2.x * m[2], a2.y * m[3], a2.z * m[3], a2.w * m[3]);
        }
    }
}

extern "C" void kernel_launch(void* const* d_in, const int* in_sizes, int n_in,
                              void* d_out, int out_size) {
    const float* images    = (const float*)d_in[0];
    const float* angles    = (const float*)d_in[1];
    const int*   gridblock = (const int*)  d_in[2];
    const int*   start1    = (const int*)  d_in[3];
    const int*   start2    = (const int*)  d_in[4];
    float* out = (float*)d_out;

    dim3 grid(HH / 8, BB);   // (64, 32)
    gridmask_kernel<<<grid, 256>>>(images, angles, gridblock, start1, start2, out);
}

// round 3
// speedup vs baseline: 1.0340x; 1.0340x over previous
#include <cuda_runtime.h>
#include <cuda_bf16.h>

#define SS   1024                 // S = 2*max(H,W)
#define HH   512
#define WW   512
#define BB   32
#define NTHREADS 512
#define BLOCKS_X 64
#define F4_PER_IMG   (HH*WW*3/4)          // 196608
#define F4_PER_BLOCK (F4_PER_IMG/BLOCKS_X) // 3072
#define F4_PER_THR   (F4_PER_BLOCK/NTHREADS) // 6

__device__ __forceinline__ float stripe_val(int i, int st, int lim,
                                            unsigned M, int gb, int length) {
    int d = i - st;
    unsigned u = (unsigned)d;
    unsigned q = (u * M) >> 22;          // exact d/gb for 0<=d<2048
    unsigned rem = u - q * (unsigned)gb;
    return (d >= 0 && d < lim && rem < (unsigned)length) ? 1.0f : 0.0f;
}

__global__ __launch_bounds__(NTHREADS, 2)
void gridmask_kernel(const float* __restrict__ img,
                     const float* __restrict__ angles,
                     const int*   __restrict__ gridblock,
                     const int*   __restrict__ start1,
                     const int*   __restrict__ start2,
                     float*       __restrict__ out) {
    __shared__ float2 rowp[SS];    // (stripe(i), stripe(i+1))
    __shared__ float2 colp[SS];
    __shared__ float  s_trig[2];

    const int b   = blockIdx.y;
    const int gb  = gridblock[b];
    const int st1 = start1[b];
    const int st2 = start2[b];

    float lf = __fadd_rn(__fmul_rn((float)gb, 0.6f), 0.5f);
    int length = (int)lf;
    length = min(max(length, 1), gb - 1);
    const int lim = (SS / gb) * gb;
    const unsigned M = (1u << 22) / (unsigned)gb + 1u;

    if (threadIdx.x == 0) {
        float a = angles[b];
        s_trig[0] = cosf(a);
        s_trig[1] = sinf(a);
    }
    for (int i = threadIdx.x; i < SS; i += NTHREADS) {
        rowp[i] = make_float2(stripe_val(i,     st1, lim, M, gb, length),
                              stripe_val(i + 1, st1, lim, M, gb, length));
        colp[i] = make_float2(stripe_val(i,     st2, lim, M, gb, length),
                              stripe_val(i + 1, st2, lim, M, gb, length));
    }
    __syncthreads();

    const float cosv = s_trig[0];
    const float sinv = s_trig[1];

    const float4* imgb4 = reinterpret_cast<const float4*>(img + (size_t)b * HH * WW * 3);
    float4*       outb4 = reinterpret_cast<float4*>(out + (size_t)b * HH * WW * 3);

    // mask at pixel p (0..262143); sampled coords provably in [150,873]:
    // rotation radius sqrt(2)*255.5 = 361.3 < 511.5, so no reflection needed.
    auto maskpix = [&](unsigned p) -> float {
        int h = (int)(p >> 9);
        int w = (int)(p & (WW - 1));
        float yy = (float)h - 255.5f;          // (h+OFFC) - 511.5
        float xx = (float)w - 255.5f;
        float sx = fmaf(cosv, xx, fmaf(sinv,  yy, 511.5f));
        float sy = fmaf(-sinv, xx, fmaf(cosv, yy, 511.5f));
        float x0f = floorf(sx), y0f = floorf(sy);
        float fx = sx - x0f,    fy = sy - y0f;
        float2 rr = rowp[(int)y0f];
        float2 cc = colp[(int)x0f];
        // binary OR with separable bilinear: m = R + C - R*C
        float R = fmaf(fy, rr.y - rr.x, rr.x);
        float C = fmaf(fx, cc.y - cc.x, cc.x);
        return fmaf(C, 1.0f - R, R);
    };

    const unsigned a0 = blockIdx.x * F4_PER_BLOCK + threadIdx.x;

    // Phase 1: masks for both pixels each float4 touches (ALU + LDS only)
    float mA[F4_PER_THR], mB[F4_PER_THR];
    int   rr3[F4_PER_THR];
    #pragma unroll
    for (int i = 0; i < F4_PER_THR; i++) {
        unsigned a  = a0 + i * NTHREADS;
        unsigned f0 = a * 4u;
        unsigned p  = f0 / 3u;               // magic-mul div
        rr3[i] = (int)(f0 - p * 3u);
        mA[i] = maskpix(p);
        mB[i] = maskpix(p + 1);
    }

    // Phase 2: fully-coalesced predicated loads, multiply, coalesced stores
    #pragma unroll
    for (int i = 0; i < F4_PER_THR; i++) {
        unsigned a = a0 + i * NTHREADS;
        float4 v = make_float4(0.f, 0.f, 0.f, 0.f);
        if (mA[i] != 0.0f || mB[i] != 0.0f)   // exact-zero: skip the read
            v = imgb4[a];
        // component -> pixel mapping by f0 mod 3:
        //   r=0: x,y,z->A  w->B ; r=1: x,y->A z,w->B ; r=2: x->A y,z,w->B
        float my = (rr3[i] == 2) ? mB[i] : mA[i];
        float mz = (rr3[i] == 0) ? mA[i] : mB[i];
        outb4[a] = make_float4(v.x * mA[i], v.y * my, v.z * mz, v.w * mB[i]);
    }
}

extern "C" void kernel_launch(void* const* d_in, const int* in_sizes, int n_in,
                              void* d_out, int out_size) {
    const float* images    = (const float*)d_in[0];
    const float* angles    = (const float*)d_in[1];
    const int*   gridblock = (const int*)  d_in[2];
    const int*   start1    = (const int*)  d_in[3];
    const int*   start2    = (const int*)  d_in[4];
    float* out = (float*)d_out;

    dim3 grid(BLOCKS_X, BB);   // (64, 32)
    gridmask_kernel<<<grid, NTHREADS>>>(images, angles, gridblock, start1, start2, out);
}

// round 4
// speedup vs baseline: 1.0546x; 1.0199x over previous
#include <cuda_runtime.h>
#include <cuda_bf16.h>

#define SS   1024
#define HH   512
#define WW   512
#define BB   32
#define NTHREADS 256
#define F4_PER_THR 4
#define F4_PER_BLOCK (NTHREADS * F4_PER_THR)         // 1024
#define F4_PER_IMG   (HH*WW*3/4)                     // 196608
#define BLOCKS_X     (F4_PER_IMG / F4_PER_BLOCK)     // 192

// Per-batch stripe LUTs: [b][0..1023]=row stripes, [b][1024..2047]=col stripes
__device__ float g_lut[BB][2 * SS];

__device__ __forceinline__ float stripe_val(int i, int st, int lim,
                                            unsigned M, int gb, int length) {
    int d = i - st;
    unsigned u = (unsigned)d;
    unsigned q = (u * M) >> 22;            // exact d/gb for 0<=d<2048
    unsigned rem = u - q * (unsigned)gb;
    return (d >= 0 && d < lim && rem < (unsigned)length) ? 1.0f : 0.0f;
}

__global__ void build_luts(const int* __restrict__ gridblock,
                           const int* __restrict__ start1,
                           const int* __restrict__ start2) {
    const int b   = blockIdx.x;
    const int gb  = gridblock[b];
    const int st1 = start1[b];
    const int st2 = start2[b];
    float lf = __fadd_rn(__fmul_rn((float)gb, 0.6f), 0.5f);
    int length = (int)lf;
    length = min(max(length, 1), gb - 1);
    const int lim = (SS / gb) * gb;
    const unsigned M = (1u << 22) / (unsigned)gb + 1u;
    for (int i = threadIdx.x; i < SS; i += blockDim.x) {
        g_lut[b][i]      = stripe_val(i, st1, lim, M, gb, length);
        g_lut[b][SS + i] = stripe_val(i, st2, lim, M, gb, length);
    }
}

__global__ __launch_bounds__(NTHREADS, 5)
void gridmask_kernel(const float* __restrict__ img,
                     const float* __restrict__ angles,
                     float*       __restrict__ out) {
    __shared__ float s_lut[2 * SS];      // [0..1023]=rowm, [1024..2047]=colm
    __shared__ float s_trig[2];

    const int b = blockIdx.y;

    // Coalesced LUT fetch from L2-resident global scratch (2 float4 / thread)
    {
        const float4* src = reinterpret_cast<const float4*>(g_lut[b]);
        float4* dst = reinterpret_cast<float4*>(s_lut);
        dst[threadIdx.x]            = src[threadIdx.x];
        dst[threadIdx.x + NTHREADS] = src[threadIdx.x + NTHREADS];
    }
    if (threadIdx.x == 0) {
        float a = angles[b];
        s_trig[0] = cosf(a);
        s_trig[1] = sinf(a);
    }
    __syncthreads();

    const float cosv = s_trig[0];
    const float sinv = s_trig[1];
    const float* rowm = s_lut;
    const float* colm = s_lut + SS;

    const float4* imgb4 = reinterpret_cast<const float4*>(img + (size_t)b * HH * WW * 3);
    float4*       outb4 = reinterpret_cast<float4*>(out + (size_t)b * HH * WW * 3);

    const unsigned a0 = blockIdx.x * F4_PER_BLOCK + threadIdx.x;

    // Phase 1: front-batched independent streaming loads (max MLP)
    float4 v[F4_PER_THR];
    #pragma unroll
    for (int i = 0; i < F4_PER_THR; i++)
        v[i] = __ldcs(&imgb4[a0 + i * NTHREADS]);

    // Phase 2: masks for the two pixels each float4 spans (hides load latency)
    // Sampled coords provably within [150,873]: rotation radius
    // sqrt(2)*255.5 = 361.3 < 511.5, so reflection never triggers.
    auto maskpix = [&](unsigned p) -> float {
        float yy = (float)(int)(p >> 9)       - 255.5f;
        float xx = (float)(int)(p & (WW - 1)) - 255.5f;
        float sx = fmaf(cosv, xx, fmaf(sinv,  yy, 511.5f));
        float sy = fmaf(-sinv, xx, fmaf(cosv, yy, 511.5f));
        float x0f = floorf(sx), y0f = floorf(sy);
        float fx = sx - x0f,    fy = sy - y0f;
        int x0 = (int)x0f, y0 = (int)y0f;
        float r0 = rowm[y0], r1 = rowm[y0 + 1];
        float c0 = colm[x0], c1 = colm[x0 + 1];
        float R = fmaf(fy, r1 - r0, r0);
        float C = fmaf(fx, c1 - c0, c0);
        return fmaf(C, 1.0f - R, R);      // binary OR: R + C - R*C
    };

    float mA[F4_PER_THR], mB[F4_PER_THR];
    int   r3[F4_PER_THR];
    #pragma unroll
    for (int i = 0; i < F4_PER_THR; i++) {
        unsigned f0 = (a0 + i * NTHREADS) * 4u;
        unsigned p  = f0 / 3u;            // compiler magic-mul
        r3[i] = (int)(f0 - p * 3u);
        mA[i] = maskpix(p);
        mB[i] = maskpix(p + 1);
    }

    // Phase 3: multiply + coalesced streaming stores
    // component->pixel by f0 mod 3:
    //   r=0: x,y,z->A w->B ; r=1: x,y->A z,w->B ; r=2: x->A y,z,w->B
    #pragma unroll
    for (int i = 0; i < F4_PER_THR; i++) {
        float my = (r3[i] == 2) ? mB[i] : mA[i];
        float mz = (r3[i] == 0) ? mA[i] : mB[i];
        float4 o = make_float4(v[i].x * mA[i], v[i].y * my,
                               v[i].z * mz,    v[i].w * mB[i]);
        __stcs(&outb4[a0 + i * NTHREADS], o);
    }
}

extern "C" void kernel_launch(void* const* d_in, const int* in_sizes, int n_in,
                              void* d_out, int out_size) {
    const float* images    = (const float*)d_in[0];
    const float* angles    = (const float*)d_in[1];
    const int*   gridblock = (const int*)  d_in[2];
    const int*   start1    = (const int*)  d_in[3];
    const int*   start2    = (const int*)  d_in[4];
    float* out = (float*)d_out;

    build_luts<<<BB, 256>>>(gridblock, start1, start2);
    dim3 grid(BLOCKS_X, BB);   // (192, 32)
    gridmask_kernel<<<grid, NTHREADS>>>(images, angles, out);
}